// round 1
// baseline (speedup 1.0000x reference)
#include <cuda_runtime.h>
#include <cstddef>

// C = tril(tril(A) @ tril(B)), N = 4096, fp32.
// Only k in [j, i] contributes to C[i,j] (i >= j). Tile-level: block (bi,bj)
// needs k-blocks [bj .. bi] only; blocks with bi < bj are identically zero.

#define NN 4096
#define BM 128
#define BN 128
#define BK 16
#define TM 8
#define TN 8

__global__ __launch_bounds__(256, 1)
void trimm_kernel(const float* __restrict__ A,
                  const float* __restrict__ B,
                  float* __restrict__ C) {
    const int bi = blockIdx.y;   // row tile
    const int bj = blockIdx.x;   // col tile
    const int tid = threadIdx.x;
    const int tx = tid & 15;     // 0..15  (col group)
    const int ty = tid >> 4;     // 0..15  (row group)

    const int rowC0 = bi * BM + ty * TM;
    const int colC0 = bj * BN + tx * TN;

    // Tiles strictly above the diagonal: output is exactly zero.
    if (bi < bj) {
        const float4 z = make_float4(0.f, 0.f, 0.f, 0.f);
#pragma unroll
        for (int m = 0; m < TM; m++) {
            float4* p = reinterpret_cast<float4*>(&C[(size_t)(rowC0 + m) * NN + colC0]);
            p[0] = z;
            p[1] = z;
        }
        return;
    }

    __shared__ float As[BK][BM];   // transposed A tile: As[k][m]
    __shared__ float Bs[BK][BN];   // Bs[k][n]

    float acc[TM][TN];
#pragma unroll
    for (int m = 0; m < TM; m++)
#pragma unroll
        for (int n = 0; n < TN; n++) acc[m][n] = 0.f;

    // Global-load index split (256 threads):
    // A tile: 128 rows x 16 k -> each thread loads 2 float4 (row = tid/4, k4 = tid%4)
    // B tile: 16 k x 128 cols -> each thread loads 2 float4 (k = tid/32, c4 = tid%32)
    const int arow = tid >> 2;   // 0..63
    const int ak4  = tid & 3;    // float4 index along k
    const int brow = tid >> 5;   // 0..7
    const int bc4  = tid & 31;   // float4 index along n

    const int kbeg = bj * BM;          // min useful k for this tile (j >= bj*128)
    const int kend = bi * BM + BM;     // max useful k + 1       (k <= i <= bi*128+127)

    for (int kb = kbeg; kb < kend; kb += BK) {
        // ---- stage A (masked: A[i,k] valid only for k <= i) ----
#pragma unroll
        for (int s = 0; s < 2; s++) {
            const int r  = arow + s * 64;
            const int gi = bi * BM + r;
            const int k0 = kb + ak4 * 4;
            const float4 v = *reinterpret_cast<const float4*>(&A[(size_t)gi * NN + k0]);
            As[ak4 * 4 + 0][r] = (k0 + 0 <= gi) ? v.x : 0.f;
            As[ak4 * 4 + 1][r] = (k0 + 1 <= gi) ? v.y : 0.f;
            As[ak4 * 4 + 2][r] = (k0 + 2 <= gi) ? v.z : 0.f;
            As[ak4 * 4 + 3][r] = (k0 + 3 <= gi) ? v.w : 0.f;
        }
        // ---- stage B (masked: B[k,j] valid only for j <= k) ----
#pragma unroll
        for (int s = 0; s < 2; s++) {
            const int r   = brow + s * 8;
            const int gk  = kb + r;
            const int gj0 = bj * BN + bc4 * 4;
            float4 v = *reinterpret_cast<const float4*>(&B[(size_t)gk * NN + gj0]);
            v.x = (gj0 + 0 <= gk) ? v.x : 0.f;
            v.y = (gj0 + 1 <= gk) ? v.y : 0.f;
            v.z = (gj0 + 2 <= gk) ? v.z : 0.f;
            v.w = (gj0 + 3 <= gk) ? v.w : 0.f;
            *reinterpret_cast<float4*>(&Bs[r][bc4 * 4]) = v;
        }
        __syncthreads();

        // ---- 8x8 register-tile FMA ----
#pragma unroll
        for (int kk = 0; kk < BK; kk++) {
            float ra[TM], rb[TN];
            *reinterpret_cast<float4*>(&ra[0]) =
                *reinterpret_cast<const float4*>(&As[kk][ty * TM + 0]);
            *reinterpret_cast<float4*>(&ra[4]) =
                *reinterpret_cast<const float4*>(&As[kk][ty * TM + 4]);
            *reinterpret_cast<float4*>(&rb[0]) =
                *reinterpret_cast<const float4*>(&Bs[kk][tx * TN + 0]);
            *reinterpret_cast<float4*>(&rb[4]) =
                *reinterpret_cast<const float4*>(&Bs[kk][tx * TN + 4]);
#pragma unroll
            for (int m = 0; m < TM; m++)
#pragma unroll
                for (int n = 0; n < TN; n++)
                    acc[m][n] = fmaf(ra[m], rb[n], acc[m][n]);
        }
        __syncthreads();
    }

    // ---- epilogue: tril mask (only semantically active on diagonal tiles) ----
#pragma unroll
    for (int m = 0; m < TM; m++) {
        const int gi = rowC0 + m;
        float4 o0, o1;
        o0.x = (gi >= colC0 + 0) ? acc[m][0] : 0.f;
        o0.y = (gi >= colC0 + 1) ? acc[m][1] : 0.f;
        o0.z = (gi >= colC0 + 2) ? acc[m][2] : 0.f;
        o0.w = (gi >= colC0 + 3) ? acc[m][3] : 0.f;
        o1.x = (gi >= colC0 + 4) ? acc[m][4] : 0.f;
        o1.y = (gi >= colC0 + 5) ? acc[m][5] : 0.f;
        o1.z = (gi >= colC0 + 6) ? acc[m][6] : 0.f;
        o1.w = (gi >= colC0 + 7) ? acc[m][7] : 0.f;
        float4* p = reinterpret_cast<float4*>(&C[(size_t)gi * NN + colC0]);
        p[0] = o0;
        p[1] = o1;
    }
}

extern "C" void kernel_launch(void* const* d_in, const int* in_sizes, int n_in,
                              void* d_out, int out_size) {
    const float* A = (const float*)d_in[0];
    const float* B = (const float*)d_in[1];
    float* C = (float*)d_out;
    (void)in_sizes; (void)n_in; (void)out_size;

    dim3 grid(NN / BN, NN / BM);
    trimm_kernel<<<grid, 256>>>(A, B, C);
}

// round 4
// speedup vs baseline: 3.8206x; 3.8206x over previous
#include <cuda_runtime.h>
#include <cuda_bf16.h>
#include <cstdint>
#include <cstddef>

// C = tril(tril(A) @ tril(B)), N=4096, fp32.
// bf16 hi/lo split (3-MMA fp32 emulation) on mma.sync.m16n8k16 (HMMA).

#define NN 4096
#define TILES 32
#define NLOWER 528   // TILES*(TILES+1)/2

// dynamic smem: aHi 16K | aLo 16K | bHi 16K (2x 8K j-halves) | bLo 16K (2x 8K)
#define OFF_ALO 16384
#define OFF_B   32768
#define OFF_BLO 16384     // relative to bHi
#define SMEM_BYTES 65536

#define SWZ(off) ((off) ^ (((off) >> 3) & 0x70))

__device__ __forceinline__ uint32_t smem_u32(const void* p) {
    uint32_t a;
    asm("{ .reg .u64 t; cvta.to.shared.u64 t, %1; cvt.u32.u64 %0, t; }" : "=r"(a) : "l"(p));
    return a;
}

// split 2 fp32 into packed bf16 hi-pair and lo-pair (low half = x0)
__device__ __forceinline__ void split2(float x0, float x1, uint32_t& h, uint32_t& l) {
    asm("cvt.rn.bf16x2.f32 %0, %1, %2;" : "=r"(h) : "f"(x1), "f"(x0));
    float hf0 = __uint_as_float(h << 16);
    float hf1 = __uint_as_float(h & 0xFFFF0000u);
    float l0 = x0 - hf0;
    float l1 = x1 - hf1;
    asm("cvt.rn.bf16x2.f32 %0, %1, %2;" : "=r"(l) : "f"(l1), "f"(l0));
}

__device__ __forceinline__ void ldsm_x4(uint32_t* r, uint32_t addr) {
    asm volatile("ldmatrix.sync.aligned.m8n8.x4.shared.b16 {%0,%1,%2,%3}, [%4];"
                 : "=r"(r[0]), "=r"(r[1]), "=r"(r[2]), "=r"(r[3]) : "r"(addr));
}
__device__ __forceinline__ void ldsm_x4_t(uint32_t* r, uint32_t addr) {
    asm volatile("ldmatrix.sync.aligned.m8n8.x4.trans.shared.b16 {%0,%1,%2,%3}, [%4];"
                 : "=r"(r[0]), "=r"(r[1]), "=r"(r[2]), "=r"(r[3]) : "r"(addr));
}

__device__ __forceinline__ void mma_bf16(float* d, const uint32_t* a, const uint32_t* b) {
    asm volatile(
        "mma.sync.aligned.m16n8k16.row.col.f32.bf16.bf16.f32 "
        "{%0,%1,%2,%3}, {%4,%5,%6,%7}, {%8,%9}, {%0,%1,%2,%3};"
        : "+f"(d[0]), "+f"(d[1]), "+f"(d[2]), "+f"(d[3])
        : "r"(a[0]), "r"(a[1]), "r"(a[2]), "r"(a[3]), "r"(b[0]), "r"(b[1]));
}

__global__ void __launch_bounds__(256, 2)
trimm_hmma(const float* __restrict__ A, const float* __restrict__ B, float* __restrict__ C) {
    extern __shared__ __align__(1024) char sm[];
    const uint32_t smb = smem_u32(sm);
    const int tid = threadIdx.x;
    const int wid = tid >> 5;
    const int lid = tid & 31;

    // ---- block id -> (bi, bj): lower triangle, longest-work first ----
    int bi, bj;
    {
        int id = blockIdx.x;
        if (id < NLOWER) {
            int d = TILES - 1, r = id;
            while (r >= TILES - d) { r -= TILES - d; d--; }
            bj = r; bi = r + d;
        } else {
            // strictly-upper tiles: exact zeros
            int z = id - NLOWER;
            int ui = 0;
            while (z >= TILES - 1 - ui) { z -= TILES - 1 - ui; ui++; }
            int uj = ui + 1 + z;
            const float4 zf = make_float4(0.f, 0.f, 0.f, 0.f);
            #pragma unroll
            for (int it = 0; it < 8; it++) {
                int gi = ui * 128 + it * 16 + (tid >> 4);
                float4* pr = reinterpret_cast<float4*>(&C[(size_t)gi * NN + uj * 128]);
                pr[(tid & 15) * 2] = zf;
                pr[(tid & 15) * 2 + 1] = zf;
            }
            return;
        }
    }

    const int mi = wid >> 1;   // 0..3 : warp row group (32 rows)
    const int nj = wid & 1;    // 0..1 : warp col group (64 cols) == B j-half

    float acc[2][8][4];
    #pragma unroll
    for (int mt = 0; mt < 2; mt++)
        #pragma unroll
        for (int nt = 0; nt < 8; nt++)
            #pragma unroll
            for (int q = 0; q < 4; q++) acc[mt][nt][q] = 0.f;

    // loader index split
    const int arow_off = tid >> 4;   // 0..15
    const int af4 = tid & 15;        // k float4 idx (0..15)
    const int bk_off = tid >> 5;     // 0..7
    const int bf4 = tid & 31;        // j float4 idx (0..31)
    const int jh = bf4 >> 4;
    const uint32_t jcol = (uint32_t)((bf4 & 15) * 8);

    // ldmatrix lane addressing (constant parts)
    const int a_r = mi * 32 + (lid & 15);          // + mt*16
    const int a_kb = (lid >> 4) * 8;               // + ks*16
    const int b_k = (lid & 7) + ((lid >> 3) & 1) * 8;  // + ks*16
    const int b_nb = (lid >> 4) * 8;               // + nt2*16
    const uint32_t bHiW = smb + OFF_B + nj * 8192;       // this warp's j-half
    const uint32_t bLoW = bHiW + OFF_BLO;

    const int nch = 2 * (bi - bj + 1);

    for (int c = 0; c < nch; c++) {
        const int kb = bj * 128 + c * 64;

        __syncthreads();   // previous mma phase done reading SMEM

        // ---- convert A chunk: 128 x 64k -> hi/lo bf16, K-major SW128 ----
        {
            char* aHi = sm;
            char* aLo = sm + OFF_ALO;
            const int k0 = kb + af4 * 4;
            #pragma unroll
            for (int it = 0; it < 8; it++) {
                const int r = it * 16 + arow_off;
                const int gi = bi * 128 + r;
                float4 v = *reinterpret_cast<const float4*>(&A[(size_t)gi * NN + k0]);
                v.x = (k0     <= gi) ? v.x : 0.f;
                v.y = (k0 + 1 <= gi) ? v.y : 0.f;
                v.z = (k0 + 2 <= gi) ? v.z : 0.f;
                v.w = (k0 + 3 <= gi) ? v.w : 0.f;
                uint32_t h01, l01, h23, l23;
                split2(v.x, v.y, h01, l01);
                split2(v.z, v.w, h23, l23);
                const uint32_t off = SWZ((uint32_t)(r * 128 + af4 * 8));
                *reinterpret_cast<uint2*>(aHi + off) = make_uint2(h01, h23);
                *reinterpret_cast<uint2*>(aLo + off) = make_uint2(l01, l23);
            }
        }
        // ---- convert B chunk: 64k x 128j -> hi/lo bf16, [k][j] SW128 halves ----
        {
            char* bHi = sm + OFF_B;
            char* bLo = bHi + OFF_BLO;
            const int gj0 = bj * 128 + bf4 * 4;
            #pragma unroll
            for (int it = 0; it < 8; it++) {
                const int kr = it * 8 + bk_off;
                const int gk = kb + kr;
                float4 v = *reinterpret_cast<const float4*>(&B[(size_t)gk * NN + gj0]);
                v.x = (gj0     <= gk) ? v.x : 0.f;
                v.y = (gj0 + 1 <= gk) ? v.y : 0.f;
                v.z = (gj0 + 2 <= gk) ? v.z : 0.f;
                v.w = (gj0 + 3 <= gk) ? v.w : 0.f;
                uint32_t h01, l01, h23, l23;
                split2(v.x, v.y, h01, l01);
                split2(v.z, v.w, h23, l23);
                const uint32_t off = (uint32_t)(jh * 8192) + SWZ((uint32_t)(kr * 128) + jcol);
                *reinterpret_cast<uint2*>(bHi + off) = make_uint2(h01, h23);
                *reinterpret_cast<uint2*>(bLo + off) = make_uint2(l01, l23);
            }
        }

        __syncthreads();

        // ---- MMA: 4 k16-steps x (hi*hi + hi*lo + lo*hi) ----
        #pragma unroll
        for (int ks = 0; ks < 4; ks++) {
            uint32_t ah[2][4], al[2][4];
            #pragma unroll
            for (int mt = 0; mt < 2; mt++) {
                const uint32_t aoff = SWZ((uint32_t)((a_r + mt * 16) * 128 + (ks * 16 + a_kb) * 2));
                ldsm_x4(ah[mt], smb + aoff);
                ldsm_x4(al[mt], smb + OFF_ALO + aoff);
            }
            #pragma unroll
            for (int nt2 = 0; nt2 < 4; nt2++) {
                uint32_t bh[4], bl[4];
                const uint32_t boff = SWZ((uint32_t)((ks * 16 + b_k) * 128 + (nt2 * 16 + b_nb) * 2));
                ldsm_x4_t(bh, bHiW + boff);
                ldsm_x4_t(bl, bLoW + boff);
                #pragma unroll
                for (int mt = 0; mt < 2; mt++) {
                    mma_bf16(acc[mt][nt2 * 2 + 0], ah[mt], bh);
                    mma_bf16(acc[mt][nt2 * 2 + 1], ah[mt], bh + 2);
                    mma_bf16(acc[mt][nt2 * 2 + 0], ah[mt], bl);
                    mma_bf16(acc[mt][nt2 * 2 + 1], ah[mt], bl + 2);
                    mma_bf16(acc[mt][nt2 * 2 + 0], al[mt], bh);
                    mma_bf16(acc[mt][nt2 * 2 + 1], al[mt], bh + 2);
                }
            }
        }
    }

    // ---- epilogue: tril-masked stores ----
    const int gcol0 = bj * 128 + nj * 64 + (lid & 3) * 2;
    const int grow0 = bi * 128 + mi * 32 + (lid >> 2);
    #pragma unroll
    for (int mt = 0; mt < 2; mt++) {
        #pragma unroll
        for (int half = 0; half < 2; half++) {
            const int gi = grow0 + mt * 16 + half * 8;
            float* crow = &C[(size_t)gi * NN];
            #pragma unroll
            for (int nt = 0; nt < 8; nt++) {
                const int gj = gcol0 + nt * 8;
                float2 o;
                o.x = (gj     <= gi) ? acc[mt][nt][half * 2 + 0] : 0.f;
                o.y = (gj + 1 <= gi) ? acc[mt][nt][half * 2 + 1] : 0.f;
                *reinterpret_cast<float2*>(crow + gj) = o;
            }
        }
    }
}

extern "C" void kernel_launch(void* const* d_in, const int* in_sizes, int n_in,
                              void* d_out, int out_size) {
    const float* A = (const float*)d_in[0];
    const float* B = (const float*)d_in[1];
    float* C = (float*)d_out;
    (void)in_sizes; (void)n_in; (void)out_size;

    cudaFuncSetAttribute(trimm_hmma, cudaFuncAttributeMaxDynamicSharedMemorySize, SMEM_BYTES);
    trimm_hmma<<<TILES * TILES, 256, SMEM_BYTES>>>(A, B, C);
}

// round 5
// speedup vs baseline: 4.3156x; 1.1296x over previous
#include <cuda_runtime.h>
#include <cuda_bf16.h>
#include <cstdint>
#include <cstddef>

// C = tril(tril(A) @ tril(B)), N=4096, fp32.
// bf16 hi/lo split (3-MMA fp32 emulation) on mma.sync.m16n8k16 (HMMA),
// software-pipelined: register prefetch (c+1) under MMA (c), double-buffered SMEM.

#define NN 4096
#define TILES 32
#define NLOWER 528   // TILES*(TILES+1)/2

// per-buffer layout (stride 64KB): aHi 16K | aLo 16K | bHi 16K (2x 8K j-halves) | bLo 16K
#define BUF_STRIDE 65536
#define OFF_ALO 16384
#define OFF_B   32768
#define OFF_BLO 16384     // relative to bHi
#define SMEM_BYTES (2 * BUF_STRIDE)

#define SWZ(off) ((off) ^ (((off) >> 3) & 0x70))

__device__ __forceinline__ uint32_t smem_u32(const void* p) {
    uint32_t a;
    asm("{ .reg .u64 t; cvta.to.shared.u64 t, %1; cvt.u32.u64 %0, t; }" : "=r"(a) : "l"(p));
    return a;
}

// split 2 fp32 into packed bf16 hi-pair and lo-pair (low half = x0)
__device__ __forceinline__ void split2(float x0, float x1, uint32_t& h, uint32_t& l) {
    asm("cvt.rn.bf16x2.f32 %0, %1, %2;" : "=r"(h) : "f"(x1), "f"(x0));
    float hf0 = __uint_as_float(h << 16);
    float hf1 = __uint_as_float(h & 0xFFFF0000u);
    float l0 = x0 - hf0;
    float l1 = x1 - hf1;
    asm("cvt.rn.bf16x2.f32 %0, %1, %2;" : "=r"(l) : "f"(l1), "f"(l0));
}

__device__ __forceinline__ void ldsm_x4(uint32_t* r, uint32_t addr) {
    asm volatile("ldmatrix.sync.aligned.m8n8.x4.shared.b16 {%0,%1,%2,%3}, [%4];"
                 : "=r"(r[0]), "=r"(r[1]), "=r"(r[2]), "=r"(r[3]) : "r"(addr));
}
__device__ __forceinline__ void ldsm_x4_t(uint32_t* r, uint32_t addr) {
    asm volatile("ldmatrix.sync.aligned.m8n8.x4.trans.shared.b16 {%0,%1,%2,%3}, [%4];"
                 : "=r"(r[0]), "=r"(r[1]), "=r"(r[2]), "=r"(r[3]) : "r"(addr));
}

__device__ __forceinline__ void mma_bf16(float* d, const uint32_t* a, const uint32_t* b) {
    asm volatile(
        "mma.sync.aligned.m16n8k16.row.col.f32.bf16.bf16.f32 "
        "{%0,%1,%2,%3}, {%4,%5,%6,%7}, {%8,%9}, {%0,%1,%2,%3};"
        : "+f"(d[0]), "+f"(d[1]), "+f"(d[2]), "+f"(d[3])
        : "r"(a[0]), "r"(a[1]), "r"(a[2]), "r"(a[3]), "r"(b[0]), "r"(b[1]));
}

__global__ void __launch_bounds__(256, 1)
trimm_hmma(const float* __restrict__ A, const float* __restrict__ B, float* __restrict__ C) {
    extern __shared__ __align__(1024) char sm[];
    const uint32_t smb = smem_u32(sm);
    const int tid = threadIdx.x;
    const int wid = tid >> 5;
    const int lid = tid & 31;

    // ---- block id -> (bi, bj): lower triangle, longest-work first ----
    int bi, bj;
    {
        int id = blockIdx.x;
        if (id < NLOWER) {
            int d = TILES - 1, r = id;
            while (r >= TILES - d) { r -= TILES - d; d--; }
            bj = r; bi = r + d;
        } else {
            // strictly-upper tiles: exact zeros
            int z = id - NLOWER;
            int ui = 0;
            while (z >= TILES - 1 - ui) { z -= TILES - 1 - ui; ui++; }
            int uj = ui + 1 + z;
            const float4 zf = make_float4(0.f, 0.f, 0.f, 0.f);
            #pragma unroll
            for (int it = 0; it < 8; it++) {
                int gi = ui * 128 + it * 16 + (tid >> 4);
                float4* pr = reinterpret_cast<float4*>(&C[(size_t)gi * NN + uj * 128]);
                pr[(tid & 15) * 2] = zf;
                pr[(tid & 15) * 2 + 1] = zf;
            }
            return;
        }
    }

    const int mi = wid >> 1;   // 0..3 : warp row group (32 rows)
    const int nj = wid & 1;    // 0..1 : warp col group (64 cols) == B j-half

    float acc[2][8][4];
    #pragma unroll
    for (int mt = 0; mt < 2; mt++)
        #pragma unroll
        for (int nt = 0; nt < 8; nt++)
            #pragma unroll
            for (int q = 0; q < 4; q++) acc[mt][nt][q] = 0.f;

    // loader index split
    const int arow_off = tid >> 4;   // 0..15
    const int af4 = tid & 15;        // k float4 idx (0..15)
    const int bk_off = tid >> 5;     // 0..7
    const int bf4 = tid & 31;        // j float4 idx (0..31)
    const int jh = bf4 >> 4;
    const uint32_t jcol = (uint32_t)((bf4 & 15) * 8);
    const int gj0 = bj * 128 + bf4 * 4;

    // ldmatrix lane addressing (constant parts)
    const int a_r = mi * 32 + (lid & 15);              // + mt*16
    const int a_kb = (lid >> 4) * 8;                   // + ks*16
    const int b_k = (lid & 7) + ((lid >> 3) & 1) * 8;  // + ks*16
    const int b_nb = (lid >> 4) * 8;                   // + nt2*16

    const int nch = 2 * (bi - bj + 1);
    const int kb0 = bj * 128;

    float4 pfA[8], pfB[8];

    // ---- prefetch: issue 16 LDG.128 for chunk c into registers ----
    auto prefetch = [&](int c) {
        const int kb = kb0 + c * 64;
        const int k0 = kb + af4 * 4;
        #pragma unroll
        for (int it = 0; it < 8; it++) {
            const int gi = bi * 128 + it * 16 + arow_off;
            pfA[it] = *reinterpret_cast<const float4*>(&A[(size_t)gi * NN + k0]);
        }
        #pragma unroll
        for (int it = 0; it < 8; it++) {
            const int gk = kb + it * 8 + bk_off;
            pfB[it] = *reinterpret_cast<const float4*>(&B[(size_t)gk * NN + gj0]);
        }
    };

    // ---- convert prefetched regs -> bf16 hi/lo SMEM buffer ----
    auto convert = [&](int c) {
        char* buf = sm + (size_t)(c & 1) * BUF_STRIDE;
        const int kb = kb0 + c * 64;
        const int k0 = kb + af4 * 4;
        char* aHi = buf;
        char* aLo = buf + OFF_ALO;
        #pragma unroll
        for (int it = 0; it < 8; it++) {
            const int r = it * 16 + arow_off;
            const int gi = bi * 128 + r;
            float4 v = pfA[it];
            v.x = (k0     <= gi) ? v.x : 0.f;
            v.y = (k0 + 1 <= gi) ? v.y : 0.f;
            v.z = (k0 + 2 <= gi) ? v.z : 0.f;
            v.w = (k0 + 3 <= gi) ? v.w : 0.f;
            uint32_t h01, l01, h23, l23;
            split2(v.x, v.y, h01, l01);
            split2(v.z, v.w, h23, l23);
            const uint32_t off = SWZ((uint32_t)(r * 128 + af4 * 8));
            *reinterpret_cast<uint2*>(aHi + off) = make_uint2(h01, h23);
            *reinterpret_cast<uint2*>(aLo + off) = make_uint2(l01, l23);
        }
        char* bHi = buf + OFF_B;
        char* bLo = bHi + OFF_BLO;
        #pragma unroll
        for (int it = 0; it < 8; it++) {
            const int kr = it * 8 + bk_off;
            const int gk = kb + kr;
            float4 v = pfB[it];
            v.x = (gj0     <= gk) ? v.x : 0.f;
            v.y = (gj0 + 1 <= gk) ? v.y : 0.f;
            v.z = (gj0 + 2 <= gk) ? v.z : 0.f;
            v.w = (gj0 + 3 <= gk) ? v.w : 0.f;
            uint32_t h01, l01, h23, l23;
            split2(v.x, v.y, h01, l01);
            split2(v.z, v.w, h23, l23);
            const uint32_t off = (uint32_t)(jh * 8192) + SWZ((uint32_t)(kr * 128) + jcol);
            *reinterpret_cast<uint2*>(bHi + off) = make_uint2(h01, h23);
            *reinterpret_cast<uint2*>(bLo + off) = make_uint2(l01, l23);
        }
    };

    // ---- prologue: fill buffer 0 ----
    prefetch(0);
    convert(0);
    __syncthreads();

    for (int c = 0; c < nch; c++) {
        const int have_next = (c + 1 < nch);
        if (have_next) prefetch(c + 1);   // LDG latency hidden under MMA below

        // ---- MMA over buffer[c&1]: 4 k16-steps x (hi*hi + hi*lo + lo*hi) ----
        {
            const uint32_t bufb = smb + (uint32_t)(c & 1) * BUF_STRIDE;
            const uint32_t bHiW = bufb + OFF_B + nj * 8192;
            const uint32_t bLoW = bHiW + OFF_BLO;
            #pragma unroll
            for (int ks = 0; ks < 4; ks++) {
                uint32_t ah[2][4], al[2][4];
                #pragma unroll
                for (int mt = 0; mt < 2; mt++) {
                    const uint32_t aoff = SWZ((uint32_t)((a_r + mt * 16) * 128 + (ks * 16 + a_kb) * 2));
                    ldsm_x4(ah[mt], bufb + aoff);
                    ldsm_x4(al[mt], bufb + OFF_ALO + aoff);
                }
                #pragma unroll
                for (int nt2 = 0; nt2 < 4; nt2++) {
                    uint32_t bh[4], bl[4];
                    const uint32_t boff = SWZ((uint32_t)((ks * 16 + b_k) * 128 + (nt2 * 16 + b_nb) * 2));
                    ldsm_x4_t(bh, bHiW + boff);
                    ldsm_x4_t(bl, bLoW + boff);
                    #pragma unroll
                    for (int mt = 0; mt < 2; mt++) {
                        mma_bf16(acc[mt][nt2 * 2 + 0], ah[mt], bh);
                        mma_bf16(acc[mt][nt2 * 2 + 1], ah[mt], bh + 2);
                        mma_bf16(acc[mt][nt2 * 2 + 0], ah[mt], bl);
                        mma_bf16(acc[mt][nt2 * 2 + 1], ah[mt], bl + 2);
                        mma_bf16(acc[mt][nt2 * 2 + 0], al[mt], bh);
                        mma_bf16(acc[mt][nt2 * 2 + 1], al[mt], bh + 2);
                    }
                }
            }
        }

        if (have_next) convert(c + 1);    // pure ALU/FMA, no memory stalls
        __syncthreads();
    }

    // ---- epilogue: tril-masked stores ----
    const int gcol0 = bj * 128 + nj * 64 + (lid & 3) * 2;
    const int grow0 = bi * 128 + mi * 32 + (lid >> 2);
    #pragma unroll
    for (int mt = 0; mt < 2; mt++) {
        #pragma unroll
        for (int half = 0; half < 2; half++) {
            const int gi = grow0 + mt * 16 + half * 8;
            float* crow = &C[(size_t)gi * NN];
            #pragma unroll
            for (int nt = 0; nt < 8; nt++) {
                const int gj = gcol0 + nt * 8;
                float2 o;
                o.x = (gj     <= gi) ? acc[mt][nt][half * 2 + 0] : 0.f;
                o.y = (gj + 1 <= gi) ? acc[mt][nt][half * 2 + 1] : 0.f;
                *reinterpret_cast<float2*>(crow + gj) = o;
            }
        }
    }
}

extern "C" void kernel_launch(void* const* d_in, const int* in_sizes, int n_in,
                              void* d_out, int out_size) {
    const float* A = (const float*)d_in[0];
    const float* B = (const float*)d_in[1];
    float* C = (float*)d_out;
    (void)in_sizes; (void)n_in; (void)out_size;

    cudaFuncSetAttribute(trimm_hmma, cudaFuncAttributeMaxDynamicSharedMemorySize, SMEM_BYTES);
    trimm_hmma<<<TILES * TILES, 256, SMEM_BYTES>>>(A, B, C);
}

// round 6
// speedup vs baseline: 4.3555x; 1.0093x over previous
#include <cuda_runtime.h>
#include <cuda_bf16.h>
#include <cstdint>
#include <cstddef>

// C = tril(tril(A) @ tril(B)), N=4096, fp32.
// bf16 hi/lo split (3-MMA fp32 emulation) on mma.sync.m16n8k16 (HMMA).
// Software pipeline with FINE-GRAINED interleave: convert piece (c+1) emitted
// between k-step MMA bursts of chunk c, so the tensor pipe never drains.

#define NN 4096
#define TILES 32
#define NLOWER 528   // TILES*(TILES+1)/2

// per-buffer layout (stride 64KB): aHi 16K | aLo 16K | bHi 16K (2x 8K j-halves) | bLo 16K
#define BUF_STRIDE 65536
#define OFF_ALO 16384
#define OFF_B   32768
#define OFF_BLO 16384     // relative to bHi
#define SMEM_BYTES (2 * BUF_STRIDE)

#define SWZ(off) ((off) ^ (((off) >> 3) & 0x70))

__device__ __forceinline__ uint32_t smem_u32(const void* p) {
    uint32_t a;
    asm("{ .reg .u64 t; cvta.to.shared.u64 t, %1; cvt.u32.u64 %0, t; }" : "=r"(a) : "l"(p));
    return a;
}

// split 2 fp32 into packed bf16 hi-pair and lo-pair (low half = x0)
__device__ __forceinline__ void split2(float x0, float x1, uint32_t& h, uint32_t& l) {
    asm("cvt.rn.bf16x2.f32 %0, %1, %2;" : "=r"(h) : "f"(x1), "f"(x0));
    float hf0 = __uint_as_float(h << 16);
    float hf1 = __uint_as_float(h & 0xFFFF0000u);
    float l0 = x0 - hf0;
    float l1 = x1 - hf1;
    asm("cvt.rn.bf16x2.f32 %0, %1, %2;" : "=r"(l) : "f"(l1), "f"(l0));
}

__device__ __forceinline__ void ldsm_x4(uint32_t* r, uint32_t addr) {
    asm volatile("ldmatrix.sync.aligned.m8n8.x4.shared.b16 {%0,%1,%2,%3}, [%4];"
                 : "=r"(r[0]), "=r"(r[1]), "=r"(r[2]), "=r"(r[3]) : "r"(addr));
}
__device__ __forceinline__ void ldsm_x4_t(uint32_t* r, uint32_t addr) {
    asm volatile("ldmatrix.sync.aligned.m8n8.x4.trans.shared.b16 {%0,%1,%2,%3}, [%4];"
                 : "=r"(r[0]), "=r"(r[1]), "=r"(r[2]), "=r"(r[3]) : "r"(addr));
}

__device__ __forceinline__ void mma_bf16(float* d, const uint32_t* a, const uint32_t* b) {
    asm volatile(
        "mma.sync.aligned.m16n8k16.row.col.f32.bf16.bf16.f32 "
        "{%0,%1,%2,%3}, {%4,%5,%6,%7}, {%8,%9}, {%0,%1,%2,%3};"
        : "+f"(d[0]), "+f"(d[1]), "+f"(d[2]), "+f"(d[3])
        : "r"(a[0]), "r"(a[1]), "r"(a[2]), "r"(a[3]), "r"(b[0]), "r"(b[1]));
}

__global__ void __launch_bounds__(256, 1)
trimm_hmma(const float* __restrict__ A, const float* __restrict__ B, float* __restrict__ C) {
    extern __shared__ __align__(1024) char sm[];
    const uint32_t smb = smem_u32(sm);
    const int tid = threadIdx.x;
    const int wid = tid >> 5;
    const int lid = tid & 31;

    // ---- block id -> (bi, bj): lower triangle, longest-work first ----
    int bi, bj;
    {
        int id = blockIdx.x;
        if (id < NLOWER) {
            int d = TILES - 1, r = id;
            while (r >= TILES - d) { r -= TILES - d; d--; }
            bj = r; bi = r + d;
        } else {
            // strictly-upper tiles: exact zeros
            int z = id - NLOWER;
            int ui = 0;
            while (z >= TILES - 1 - ui) { z -= TILES - 1 - ui; ui++; }
            int uj = ui + 1 + z;
            const float4 zf = make_float4(0.f, 0.f, 0.f, 0.f);
            #pragma unroll
            for (int it = 0; it < 8; it++) {
                int gi = ui * 128 + it * 16 + (tid >> 4);
                float4* pr = reinterpret_cast<float4*>(&C[(size_t)gi * NN + uj * 128]);
                pr[(tid & 15) * 2] = zf;
                pr[(tid & 15) * 2 + 1] = zf;
            }
            return;
        }
    }

    const int mi = wid >> 1;   // 0..3 : warp row group (32 rows)
    const int nj = wid & 1;    // 0..1 : warp col group (64 cols) == B j-half

    float acc[2][8][4];
    #pragma unroll
    for (int mt = 0; mt < 2; mt++)
        #pragma unroll
        for (int nt = 0; nt < 8; nt++)
            #pragma unroll
            for (int q = 0; q < 4; q++) acc[mt][nt][q] = 0.f;

    // loader index split
    const int arow_off = tid >> 4;   // 0..15
    const int af4 = tid & 15;        // k float4 idx (0..15)
    const int bk_off = tid >> 5;     // 0..7
    const int bf4 = tid & 31;        // j float4 idx (0..31)
    const int jh = bf4 >> 4;
    const uint32_t jcol = (uint32_t)((bf4 & 15) * 8);
    const int gj0 = bj * 128 + bf4 * 4;

    // ldmatrix lane addressing (constant parts)
    const int a_r = mi * 32 + (lid & 15);              // + mt*16
    const int a_kb = (lid >> 4) * 8;                   // + ks*16
    const int b_k = (lid & 7) + ((lid >> 3) & 1) * 8;  // + ks*16
    const int b_nb = (lid >> 4) * 8;                   // + nt2*16

    const int nch = 2 * (bi - bj + 1);
    const int kb0 = bj * 128;

    float4 pfA[8], pfB[8];

    // ---- prefetch: issue 16 LDG.128 for chunk c into registers ----
    auto prefetch = [&](int c) {
        const int kb = kb0 + c * 64;
        const int k0 = kb + af4 * 4;
        #pragma unroll
        for (int it = 0; it < 8; it++) {
            const int gi = bi * 128 + it * 16 + arow_off;
            pfA[it] = *reinterpret_cast<const float4*>(&A[(size_t)gi * NN + k0]);
        }
        #pragma unroll
        for (int it = 0; it < 8; it++) {
            const int gk = kb + it * 8 + bk_off;
            pfB[it] = *reinterpret_cast<const float4*>(&B[(size_t)gk * NN + gj0]);
        }
    };

    // ---- convert piece p (A iters 2p,2p+1 and B iters 2p,2p+1) of chunk c ----
    auto convert_piece = [&](int c, int p) {
        char* buf = sm + (size_t)(c & 1) * BUF_STRIDE;
        const int kb = kb0 + c * 64;
        const int k0 = kb + af4 * 4;
        char* aHi = buf;
        char* aLo = buf + OFF_ALO;
        char* bHi = buf + OFF_B;
        char* bLo = bHi + OFF_BLO;
        #pragma unroll
        for (int s = 0; s < 2; s++) {
            const int it = p * 2 + s;
            {
                const int r = it * 16 + arow_off;
                const int gi = bi * 128 + r;
                float4 v = pfA[it];
                v.x = (k0     <= gi) ? v.x : 0.f;
                v.y = (k0 + 1 <= gi) ? v.y : 0.f;
                v.z = (k0 + 2 <= gi) ? v.z : 0.f;
                v.w = (k0 + 3 <= gi) ? v.w : 0.f;
                uint32_t h01, l01, h23, l23;
                split2(v.x, v.y, h01, l01);
                split2(v.z, v.w, h23, l23);
                const uint32_t off = SWZ((uint32_t)(r * 128 + af4 * 8));
                *reinterpret_cast<uint2*>(aHi + off) = make_uint2(h01, h23);
                *reinterpret_cast<uint2*>(aLo + off) = make_uint2(l01, l23);
            }
            {
                const int kr = it * 8 + bk_off;
                const int gk = kb + kr;
                float4 v = pfB[it];
                v.x = (gj0     <= gk) ? v.x : 0.f;
                v.y = (gj0 + 1 <= gk) ? v.y : 0.f;
                v.z = (gj0 + 2 <= gk) ? v.z : 0.f;
                v.w = (gj0 + 3 <= gk) ? v.w : 0.f;
                uint32_t h01, l01, h23, l23;
                split2(v.x, v.y, h01, l01);
                split2(v.z, v.w, h23, l23);
                const uint32_t off = (uint32_t)(jh * 8192) + SWZ((uint32_t)(kr * 128) + jcol);
                *reinterpret_cast<uint2*>(bHi + off) = make_uint2(h01, h23);
                *reinterpret_cast<uint2*>(bLo + off) = make_uint2(l01, l23);
            }
        }
    };

    // ---- prologue: fill buffer 0 ----
    prefetch(0);
    #pragma unroll
    for (int p = 0; p < 4; p++) convert_piece(0, p);
    __syncthreads();

    for (int c = 0; c < nch; c++) {
        const int have_next = (c + 1 < nch);
        if (have_next) prefetch(c + 1);   // 16 LDG.128, latency hidden under MMA

        const uint32_t bufb = smb + (uint32_t)(c & 1) * BUF_STRIDE;
        const uint32_t bHiW = bufb + OFF_B + nj * 8192;
        const uint32_t bLoW = bHiW + OFF_BLO;

        // ---- 4 k16-steps; after each 48-HMMA burst, emit one convert piece ----
        #pragma unroll
        for (int ks = 0; ks < 4; ks++) {
            uint32_t ah[2][4], al[2][4];
            #pragma unroll
            for (int mt = 0; mt < 2; mt++) {
                const uint32_t aoff = SWZ((uint32_t)((a_r + mt * 16) * 128 + (ks * 16 + a_kb) * 2));
                ldsm_x4(ah[mt], bufb + aoff);
                ldsm_x4(al[mt], bufb + OFF_ALO + aoff);
            }
            #pragma unroll
            for (int nt2 = 0; nt2 < 4; nt2++) {
                uint32_t bh[4], bl[4];
                const uint32_t boff = SWZ((uint32_t)((ks * 16 + b_k) * 128 + (nt2 * 16 + b_nb) * 2));
                ldsm_x4_t(bh, bHiW + boff);
                ldsm_x4_t(bl, bLoW + boff);
                #pragma unroll
                for (int mt = 0; mt < 2; mt++) {
                    mma_bf16(acc[mt][nt2 * 2 + 0], ah[mt], bh);
                    mma_bf16(acc[mt][nt2 * 2 + 1], ah[mt], bh + 2);
                    mma_bf16(acc[mt][nt2 * 2 + 0], ah[mt], bl);
                    mma_bf16(acc[mt][nt2 * 2 + 1], ah[mt], bl + 2);
                    mma_bf16(acc[mt][nt2 * 2 + 0], al[mt], bh);
                    mma_bf16(acc[mt][nt2 * 2 + 1], al[mt], bh + 2);
                }
            }
            if (have_next) convert_piece(c + 1, ks);   // overlaps with queued HMMAs
        }

        __syncthreads();
    }

    // ---- epilogue: tril-masked stores ----
    const int gcol0 = bj * 128 + nj * 64 + (lid & 3) * 2;
    const int grow0 = bi * 128 + mi * 32 + (lid >> 2);
    #pragma unroll
    for (int mt = 0; mt < 2; mt++) {
        #pragma unroll
        for (int half = 0; half < 2; half++) {
            const int gi = grow0 + mt * 16 + half * 8;
            float* crow = &C[(size_t)gi * NN];
            #pragma unroll
            for (int nt = 0; nt < 8; nt++) {
                const int gj = gcol0 + nt * 8;
                float2 o;
                o.x = (gj     <= gi) ? acc[mt][nt][half * 2 + 0] : 0.f;
                o.y = (gj + 1 <= gi) ? acc[mt][nt][half * 2 + 1] : 0.f;
                *reinterpret_cast<float2*>(crow + gj) = o;
            }
        }
    }
}

extern "C" void kernel_launch(void* const* d_in, const int* in_sizes, int n_in,
                              void* d_out, int out_size) {
    const float* A = (const float*)d_in[0];
    const float* B = (const float*)d_in[1];
    float* C = (float*)d_out;
    (void)in_sizes; (void)n_in; (void)out_size;

    cudaFuncSetAttribute(trimm_hmma, cudaFuncAttributeMaxDynamicSharedMemorySize, SMEM_BYTES);
    trimm_hmma<<<TILES * TILES, 256, SMEM_BYTES>>>(A, B, C);
}